// round 17
// baseline (speedup 1.0000x reference)
#include <cuda_runtime.h>
#include <cuda_bf16.h>
#include <cuda_fp16.h>
#include <cstdint>
#include <cstddef>

#define S 2048
#define E 1024
#define H 16
#define HD 64
#define NT 16
#define SCALE 0.125f

// fp32 scratch
__device__ float g_q[S * E];
__device__ float g_k[S * E];
__device__ float g_v[S * E];
__device__ float g_rel[S * S];
__device__ float g_attn[S * E];
// fp16 hi-only pre-swizzled k/v tile images (fused), 16KB/tile
__device__ __align__(128) char g_kt[H * NT * 16384];
__device__ __align__(128) char g_vt[H * NT * 16384];
// fp16 hi/lo pre-swizzled GEMM operand images
__device__ __align__(128) char g_xi[3u * 8388608u];
__device__ __align__(128) char g_wi[4u * 4194304u];
__device__ __align__(128) char g_simAi[524288];
__device__ __align__(128) char g_simBi[524288];
__device__ __align__(128) char g_atti[8388608];

// ---------------------------------------------------------------------------
// Helpers
// ---------------------------------------------------------------------------
__device__ __forceinline__ uint32_t smem_u32(const void* p) {
    uint32_t a;
    asm("{ .reg .u64 t; cvta.to.shared.u64 t, %1; cvt.u32.u64 %0, t; }"
        : "=r"(a) : "l"(p));
    return a;
}

__device__ __forceinline__ uint32_t sw128(uint32_t off) {
    return off ^ ((off >> 3) & 0x70);
}

__device__ __forceinline__ void ldsm4(uint32_t* r, uint32_t addr) {
    asm volatile("ldmatrix.sync.aligned.m8n8.x4.shared.b16 {%0,%1,%2,%3}, [%4];"
                 : "=r"(r[0]), "=r"(r[1]), "=r"(r[2]), "=r"(r[3]) : "r"(addr));
}

__device__ __forceinline__ void mma_h32(float* c, const uint32_t* a, const uint32_t* b) {
    asm volatile(
        "mma.sync.aligned.m16n8k16.row.col.f32.f16.f16.f32 "
        "{%0,%1,%2,%3}, {%4,%5,%6,%7}, {%8,%9}, {%0,%1,%2,%3};"
        : "+f"(c[0]), "+f"(c[1]), "+f"(c[2]), "+f"(c[3])
        : "r"(a[0]), "r"(a[1]), "r"(a[2]), "r"(a[3]), "r"(b[0]), "r"(b[1]));
}

__device__ __forceinline__ void mma_h16(uint32_t* c, const uint32_t* a, const uint32_t* b) {
    asm volatile(
        "mma.sync.aligned.m16n8k16.row.col.f16.f16.f16.f16 "
        "{%0,%1}, {%2,%3,%4,%5}, {%6,%7}, {%0,%1};"
        : "+r"(c[0]), "+r"(c[1])
        : "r"(a[0]), "r"(a[1]), "r"(a[2]), "r"(a[3]), "r"(b[0]), "r"(b[1]));
}

__device__ __forceinline__ void split2h(float x, float y, uint32_t& hi, uint32_t& lo) {
    __half2 hp = __floats2half2_rn(x, y);
    float rx = x - __half2float(__low2half(hp));
    float ry = y - __half2float(__high2half(hp));
    __half2 lp = __floats2half2_rn(rx, ry);
    hi = *(uint32_t*)&hp;
    lo = *(uint32_t*)&lp;
}

__device__ __forceinline__ void split_store_h(char* base, int row, int col2,
                                              float x0, float x1) {
    uint32_t hi, lo;
    split2h(x0, x1, hi, lo);
    *(uint32_t*)(base + sw128(row * 128 + col2 * 2)) = hi;
    *(uint32_t*)(base + sw128(row * 128 + 64 + col2 * 2)) = lo;
}

#define CP16(dst, src) \
    asm volatile("cp.async.cg.shared.global [%0], [%1], 16;" :: "r"(dst), "l"(src))
#define CP_COMMIT() asm volatile("cp.async.commit_group;" ::: "memory")
#define CP_WAIT(n)  asm volatile("cp.async.wait_group %0;" :: "n"(n) : "memory")

// ---------------------------------------------------------------------------
// prep_all: operands -> fp16 hi/lo swizzled tile images. grid (32,32,9), 256t.
// ---------------------------------------------------------------------------
__global__ __launch_bounds__(256) void prep_all(
    const float* __restrict__ q, const float* __restrict__ k,
    const float* __restrict__ v,
    const float* __restrict__ Wq, const float* __restrict__ Wk,
    const float* __restrict__ Wv, const float* __restrict__ Wo,
    const float* __restrict__ sim)
{
    const int kc = blockIdx.x, rb = blockIdx.y, z = blockIdx.z;
    const float* src;
    char* dst;
    int ld, numKC, numRB, rows;
    if (z < 3) {
        src = (z == 0) ? q : (z == 1) ? k : v;
        ld = E; numKC = 32; numRB = 16; rows = 128;
        dst = g_xi + (size_t)z * 8388608u + ((size_t)rb * 32 + kc) * 16384;
    } else if (z < 7) {
        src = (z == 3) ? Wq : (z == 4) ? Wk : (z == 5) ? Wv : Wo;
        ld = E; numKC = 32; numRB = 16; rows = 64;
        dst = g_wi + (size_t)(z - 3) * 4194304u + ((size_t)rb * 32 + kc) * 8192;
    } else if (z == 7) {
        src = sim; ld = 64; numKC = 2; numRB = 16; rows = 128;
        dst = g_simAi + ((size_t)rb * 2 + kc) * 16384;
    } else {
        src = sim; ld = 64; numKC = 2; numRB = 32; rows = 64;
        dst = g_simBi + ((size_t)rb * 2 + kc) * 8192;
    }
    if (kc >= numKC || rb >= numRB) return;

    const int iters = rows * 16 / 256;
    const int tid = threadIdx.x;
    for (int s = 0; s < iters; s++) {
        int idx = s * 256 + tid;
        int r = idx >> 4, p = idx & 15;
        float2 val = *(const float2*)&src[(size_t)(rb * rows + r) * ld + kc * 32 + 2 * p];
        split_store_h(dst, r, 2 * p, val.x, val.y);
    }
}

__global__ __launch_bounds__(256) void prep_attn()
{
    const int kc = blockIdx.x, rb = blockIdx.y;
    char* dst = g_atti + ((size_t)rb * 32 + kc) * 16384;
    const int tid = threadIdx.x;
#pragma unroll
    for (int s = 0; s < 8; s++) {
        int idx = s * 256 + tid;
        int r = idx >> 4, p = idx & 15;
        float2 val = *(const float2*)&g_attn[(size_t)(rb * 128 + r) * E + kc * 32 + 2 * p];
        split_store_h(dst, r, 2 * p, val.x, val.y);
    }
}

// ---------------------------------------------------------------------------
// Image GEMM body (unchanged from R16, passing)
// ---------------------------------------------------------------------------
__device__ __forceinline__ void gemm_img_body(
    const char* __restrict__ Ai, const char* __restrict__ Bi,
    float* __restrict__ C, int numKC, int ldc, const float* __restrict__ bias,
    int row0, int col0)
{
    __shared__ __align__(128) char smA[2][16384];
    __shared__ __align__(128) char smB[2][8192];

    const int tid = threadIdx.x;
    const int warp = tid >> 5, lane = tid & 31;
    const int wm0 = (warp >> 1) * 32;
    const int wn0 = (warp & 1) * 32;

    const uint32_t sAb[2] = {smem_u32(smA[0]), smem_u32(smA[1])};
    const uint32_t sBb[2] = {smem_u32(smB[0]), smem_u32(smB[1])};

    float c[2][4][4];
    uint32_t cx[2][4][2];
#pragma unroll
    for (int i = 0; i < 2; i++)
#pragma unroll
        for (int j = 0; j < 4; j++) {
#pragma unroll
            for (int t = 0; t < 4; t++) c[i][j][t] = 0.f;
            cx[i][j][0] = 0u; cx[i][j][1] = 0u;
        }

    const int arow = wm0 + (lane & 15);
    const int acolq = (lane >> 4) * 8;
    const int bn = wn0 + (lane & 7) + ((lane >> 4) << 3);
    const int bkq = ((lane >> 3) & 1) * 8;

#pragma unroll
    for (int i = 0; i < 4; i++) {
        uint32_t off = (uint32_t)(tid + i * 256) * 16;
        CP16(sAb[0] + off, Ai + off);
    }
#pragma unroll
    for (int i = 0; i < 2; i++) {
        uint32_t off = (uint32_t)(tid + i * 256) * 16;
        CP16(sBb[0] + off, Bi + off);
    }
    CP_COMMIT();

    for (int kc = 0; kc < numKC; kc++) {
        if (kc + 1 < numKC) {
            const char* an = Ai + (size_t)(kc + 1) * 16384;
            const char* bns = Bi + (size_t)(kc + 1) * 8192;
            uint32_t dA = sAb[(kc + 1) & 1];
            uint32_t dB = sBb[(kc + 1) & 1];
#pragma unroll
            for (int i = 0; i < 4; i++) {
                uint32_t off = (uint32_t)(tid + i * 256) * 16;
                CP16(dA + off, an + off);
            }
#pragma unroll
            for (int i = 0; i < 2; i++) {
                uint32_t off = (uint32_t)(tid + i * 256) * 16;
                CP16(dB + off, bns + off);
            }
            CP_COMMIT();
            CP_WAIT(1);
        } else {
            CP_WAIT(0);
        }
        __syncthreads();

        const uint32_t sA = sAb[kc & 1];
        const uint32_t sB = sBb[kc & 1];

#pragma unroll
        for (int ks = 0; ks < 2; ks++) {
            uint32_t ca = (uint32_t)((ks * 16 + acolq) * 2);
            uint32_t ah0[4], ah1[4], al0[4], al1[4];
            ldsm4(ah0, sA + sw128((uint32_t)(arow * 128) + ca));
            ldsm4(ah1, sA + sw128((uint32_t)((arow + 16) * 128) + ca));
            ldsm4(al0, sA + sw128((uint32_t)(arow * 128 + 64) + ca));
            ldsm4(al1, sA + sw128((uint32_t)((arow + 16) * 128 + 64) + ca));

            uint32_t cb = (uint32_t)((ks * 16 + bkq) * 2);
            uint32_t bh[2][4], bl[2][4];
#pragma unroll
            for (int j2 = 0; j2 < 2; j2++) {
                ldsm4(bh[j2], sB + sw128((uint32_t)((bn + j2 * 16) * 128) + cb));
                ldsm4(bl[j2], sB + sw128((uint32_t)((bn + j2 * 16) * 128 + 64) + cb));
            }
#pragma unroll
            for (int i = 0; i < 2; i++) {
                const uint32_t* aih = (i == 0) ? ah0 : ah1;
                const uint32_t* ail = (i == 0) ? al0 : al1;
#pragma unroll
                for (int j = 0; j < 4; j++) {
                    const uint32_t* bhf = &bh[j >> 1][(j & 1) * 2];
                    const uint32_t* blf = &bl[j >> 1][(j & 1) * 2];
                    mma_h32(c[i][j], aih, bhf);
                    mma_h16(cx[i][j], aih, blf);
                    mma_h16(cx[i][j], ail, bhf);
                }
            }
        }
        __syncthreads();
    }

    const int g = lane >> 2, t4 = lane & 3;
#pragma unroll
    for (int i = 0; i < 2; i++) {
#pragma unroll
        for (int j = 0; j < 4; j++) {
            int gr0 = row0 + wm0 + i * 16 + g;
            int gc = col0 + wn0 + j * 8 + t4 * 2;
            float2 x0 = __half22float2(*(__half2*)&cx[i][j][0]);
            float2 x1 = __half22float2(*(__half2*)&cx[i][j][1]);
            float v0 = c[i][j][0] + x0.x, v1 = c[i][j][1] + x0.y;
            float v2 = c[i][j][2] + x1.x, v3 = c[i][j][3] + x1.y;
            if (bias) {
                float2 bv = *(const float2*)&bias[gc];
                v0 += bv.x; v1 += bv.y; v2 += bv.x; v3 += bv.y;
            }
            *(float2*)&C[(size_t)gr0 * ldc + gc] = make_float2(v0, v1);
            *(float2*)&C[(size_t)(gr0 + 8) * ldc + gc] = make_float2(v2, v3);
        }
    }
}

__global__ __launch_bounds__(256) void tc_gemm_img(
    const char* __restrict__ Ai, const char* __restrict__ Bi,
    float* __restrict__ C, int numKC, int ldc, const float* __restrict__ bias)
{
    gemm_img_body(Ai + ((size_t)blockIdx.y * numKC) * 16384,
                  Bi + ((size_t)blockIdx.x * numKC) * 8192,
                  C, numKC, ldc, bias, blockIdx.y * 128, blockIdx.x * 64);
}

__global__ __launch_bounds__(256) void proj_img(
    const float* __restrict__ bq, const float* __restrict__ bk,
    const float* __restrict__ bv)
{
    const int z = blockIdx.z;
    const float* bias = (z == 0) ? bq : (z == 1) ? bk : bv;
    float* C = (z == 0) ? g_q : (z == 1) ? g_k : g_v;
    gemm_img_body(g_xi + (size_t)z * 8388608u + ((size_t)blockIdx.y * 32) * 16384,
                  g_wi + (size_t)z * 4194304u + ((size_t)blockIdx.x * 32) * 8192,
                  C, 32, E, bias, blockIdx.y * 128, blockIdx.x * 64);
}

// ---------------------------------------------------------------------------
// prep_kv (unchanged)
// ---------------------------------------------------------------------------
__global__ __launch_bounds__(128) void prep_kv()
{
    const int tid = threadIdx.x;
    const int t0 = blockIdx.x * 128;
    const int h = blockIdx.y;
    const int qc0 = h * HD;
    char* kimg = g_kt + ((size_t)(h * NT + blockIdx.x)) * 16384;
    char* vimg = g_vt + ((size_t)(h * NT + blockIdx.x)) * 16384;

    const int lr = tid >> 4, lp = tid & 15;
#pragma unroll 4
    for (int s = 0; s < 16; s++) {
        int tr = s * 8 + lr;
        float4 kv = *(const float4*)&g_k[(size_t)(t0 + tr) * E + qc0 + 4 * lp];
        __half2 h01 = __floats2half2_rn(kv.x, kv.y);
        __half2 h23 = __floats2half2_rn(kv.z, kv.w);
        *(uint2*)(kimg + sw128(tr * 128 + 8 * lp)) =
            make_uint2(*(uint32_t*)&h01, *(uint32_t*)&h23);

        float4 vv = *(const float4*)&g_v[(size_t)(t0 + tr) * E + qc0 + 4 * lp];
        int sub = tr >> 6, tc = tr & 63;
        char* bh_ = vimg + sub * 8192;
        float vs[4] = {vv.x, vv.y, vv.z, vv.w};
#pragma unroll
        for (int j = 0; j < 4; j++) {
            int d = 4 * lp + j;
            *(__half*)(bh_ + sw128(d * 128 + tc * 2)) = __float2half_rn(vs[j]);
        }
    }
}

// ---------------------------------------------------------------------------
// fused_attn: as R16 but PV cross-term (ox) is CHUNK-LOCAL, folded into fp32
// o at the end of each chunk; min 3 CTAs/SM forced.
// ---------------------------------------------------------------------------
__global__ __launch_bounds__(128, 3) void fused_attn(
    const float* __restrict__ rel, float* __restrict__ wout)
{
    extern __shared__ char dyn[];
    const uint32_t smb = smem_u32(dyn);
    const uint32_t vbuf = smb + 32768;

    const int tid = threadIdx.x;
    const int warp = tid >> 5, lane = tid & 31;
    const int wm = warp >> 1, wn = warp & 1;
    const int g = lane >> 2, t4 = lane & 3;
    const int h = blockIdx.y;
    const int row0 = blockIdx.x * 64;
    const int qc0 = h * HD;

    const int rA = row0 + wm * 32 + g;
    const int rB = rA + 8, rC = rA + 16, rD = rA + 24;

    uint32_t qh[4][2][4], ql[4][2][4];
#pragma unroll
    for (int ks = 0; ks < 4; ks++) {
        int c = qc0 + ks * 16 + 2 * t4;
#pragma unroll
        for (int blk = 0; blk < 2; blk++) {
            int ra = rA + blk * 16, rb = rB + blk * 16;
            float2 x00 = *(const float2*)&g_q[(size_t)ra * E + c];
            float2 x10 = *(const float2*)&g_q[(size_t)rb * E + c];
            float2 x01 = *(const float2*)&g_q[(size_t)ra * E + c + 8];
            float2 x11 = *(const float2*)&g_q[(size_t)rb * E + c + 8];
            split2h(x00.x * SCALE, x00.y * SCALE, qh[ks][blk][0], ql[ks][blk][0]);
            split2h(x10.x * SCALE, x10.y * SCALE, qh[ks][blk][1], ql[ks][blk][1]);
            split2h(x01.x * SCALE, x01.y * SCALE, qh[ks][blk][2], ql[ks][blk][2]);
            split2h(x11.x * SCALE, x11.y * SCALE, qh[ks][blk][3], ql[ks][blk][3]);
        }
    }

    const int bnp = (lane & 7) + ((lane >> 4) << 3);
    const int bkq = ((lane >> 3) & 1) * 8;
    const int tco = wn * 64;

    const char* ksrc = g_kt + ((size_t)h * NT) * 16384;
    const char* vsrc = g_vt + ((size_t)h * NT) * 16384;

    float lA = 0.f, lB = 0.f, lC = 0.f, lD = 0.f;

    // PASS 1
#pragma unroll
    for (int i = 0; i < 8; i++) {
        uint32_t off = (uint32_t)(tid + i * 128) * 16;
        CP16(smb + off, ksrc + off);
    }
    CP_COMMIT();

#pragma unroll 1
    for (int t = 0; t < NT; t++) {
        CP_WAIT(0);
        __syncthreads();
        if (t + 1 < NT) {
            const char* src = ksrc + (size_t)(t + 1) * 16384;
            uint32_t dst = smb + ((t + 1) & 1) * 16384;
#pragma unroll
            for (int i = 0; i < 8; i++) {
                uint32_t off = (uint32_t)(tid + i * 128) * 16;
                CP16(dst + off, src + off);
            }
            CP_COMMIT();
        }
        const uint32_t uSkh = smb + (t & 1) * 16384;

#pragma unroll 1
        for (int ch = 0; ch < 4; ch++) {
            int tc = tco + ch * 16;
            int cg = t * 128 + tc + 2 * t4;
            float2 r00 = *(const float2*)&rel[(size_t)rA * S + cg];
            float2 r01 = *(const float2*)&rel[(size_t)rA * S + cg + 8];
            float2 r10 = *(const float2*)&rel[(size_t)rB * S + cg];
            float2 r11 = *(const float2*)&rel[(size_t)rB * S + cg + 8];
            float2 r20 = *(const float2*)&rel[(size_t)rC * S + cg];
            float2 r21 = *(const float2*)&rel[(size_t)rC * S + cg + 8];
            float2 r30 = *(const float2*)&rel[(size_t)rD * S + cg];
            float2 r31 = *(const float2*)&rel[(size_t)rD * S + cg + 8];

            float cs[2][2][4];
#pragma unroll
            for (int i = 0; i < 2; i++)
#pragma unroll
                for (int j = 0; j < 2; j++)
#pragma unroll
                    for (int q2 = 0; q2 < 4; q2++) cs[i][j][q2] = 0.f;

            int brow = tc + bnp;
#pragma unroll
            for (int ks = 0; ks < 4; ks++) {
                uint32_t bh[4];
                ldsm4(bh, uSkh + sw128((uint32_t)(brow * 128 + (ks * 16 + bkq) * 2)));
                mma_h32(cs[0][0], qh[ks][0], bh + 0);
                mma_h32(cs[0][1], qh[ks][0], bh + 2);
                mma_h32(cs[1][0], qh[ks][1], bh + 0);
                mma_h32(cs[1][1], qh[ks][1], bh + 2);
            }
            lA += __expf(cs[0][0][0] + r00.x * SCALE) + __expf(cs[0][0][1] + r00.y * SCALE) +
                  __expf(cs[0][1][0] + r01.x * SCALE) + __expf(cs[0][1][1] + r01.y * SCALE);
            lB += __expf(cs[0][0][2] + r10.x * SCALE) + __expf(cs[0][0][3] + r10.y * SCALE) +
                  __expf(cs[0][1][2] + r11.x * SCALE) + __expf(cs[0][1][3] + r11.y * SCALE);
            lC += __expf(cs[1][0][0] + r20.x * SCALE) + __expf(cs[1][0][1] + r20.y * SCALE) +
                  __expf(cs[1][1][0] + r21.x * SCALE) + __expf(cs[1][1][1] + r21.y * SCALE);
            lD += __expf(cs[1][0][2] + r30.x * SCALE) + __expf(cs[1][0][3] + r30.y * SCALE) +
                  __expf(cs[1][1][2] + r31.x * SCALE) + __expf(cs[1][1][3] + r31.y * SCALE);
        }
    }

    lA += __shfl_xor_sync(0xffffffffu, lA, 1);
    lA += __shfl_xor_sync(0xffffffffu, lA, 2);
    lB += __shfl_xor_sync(0xffffffffu, lB, 1);
    lB += __shfl_xor_sync(0xffffffffu, lB, 2);
    lC += __shfl_xor_sync(0xffffffffu, lC, 1);
    lC += __shfl_xor_sync(0xffffffffu, lC, 2);
    lD += __shfl_xor_sync(0xffffffffu, lD, 1);
    lD += __shfl_xor_sync(0xffffffffu, lD, 2);

    float* sml = (float*)(dyn + 32768);
    __syncthreads();
    if (t4 == 0) {
        sml[wn * 64 + wm * 32 + g]      = lA;
        sml[wn * 64 + wm * 32 + g + 8]  = lB;
        sml[wn * 64 + wm * 32 + g + 16] = lC;
        sml[wn * 64 + wm * 32 + g + 24] = lD;
    }
    __syncthreads();
    const float invA = 1.f / (sml[wm * 32 + g]      + sml[64 + wm * 32 + g]);
    const float invB = 1.f / (sml[wm * 32 + g + 8]  + sml[64 + wm * 32 + g + 8]);
    const float invC = 1.f / (sml[wm * 32 + g + 16] + sml[64 + wm * 32 + g + 16]);
    const float invD = 1.f / (sml[wm * 32 + g + 24] + sml[64 + wm * 32 + g + 24]);
    __syncthreads();

    float o[2][8][4];
#pragma unroll
    for (int i = 0; i < 2; i++)
#pragma unroll
        for (int j = 0; j < 8; j++)
#pragma unroll
            for (int q2 = 0; q2 < 4; q2++) o[i][j][q2] = 0.f;

    float* wrow = wout + (size_t)h * S * S;

    // PASS 2
#pragma unroll
    for (int i = 0; i < 8; i++) {
        uint32_t off = (uint32_t)(tid + i * 128) * 16;
        CP16(smb + off, ksrc + off);
    }
    CP_COMMIT();

#pragma unroll 1
    for (int t = 0; t < NT; t++) {
        {
            const char* srcv = vsrc + (size_t)t * 16384;
#pragma unroll
            for (int i = 0; i < 8; i++) {
                uint32_t off = (uint32_t)(tid + i * 128) * 16;
                CP16(vbuf + off, srcv + off);
            }
            CP_COMMIT();
        }
        if (t + 1 < NT) {
            const char* src = ksrc + (size_t)(t + 1) * 16384;
            uint32_t dst = smb + ((t + 1) & 1) * 16384;
#pragma unroll
            for (int i = 0; i < 8; i++) {
                uint32_t off = (uint32_t)(tid + i * 128) * 16;
                CP16(dst + off, src + off);
            }
            CP_COMMIT();
        }
        if (t + 1 < NT) { CP_WAIT(1); } else { CP_WAIT(0); }
        __syncthreads();

        const uint32_t uSkh = smb + (t & 1) * 16384;

#pragma unroll 1
        for (int ch = 0; ch < 4; ch++) {
            int tc = tco + ch * 16;
            int cg = t * 128 + tc + 2 * t4;
            float2 r00 = *(const float2*)&rel[(size_t)rA * S + cg];
            float2 r01 = *(const float2*)&rel[(size_t)rA * S + cg + 8];
            float2 r10 = *(const float2*)&rel[(size_t)rB * S + cg];
            float2 r11 = *(const float2*)&rel[(size_t)rB * S + cg + 8];
            float2 r20 = *(const float2*)&rel[(size_t)rC * S + cg];
            float2 r21 = *(const float2*)&rel[(size_t)rC * S + cg + 8];
            float2 r30 = *(const float2*)&rel[(size_t)rD * S + cg];
            float2 r31 = *(const float2*)&rel[(size_t)rD * S + cg + 8];

            float cs[2][2][4];
            uint32_t cx[2][2][2];
#pragma unroll
            for (int i = 0; i < 2; i++)
#pragma unroll
                for (int j = 0; j < 2; j++) {
#pragma unroll
                    for (int q2 = 0; q2 < 4; q2++) cs[i][j][q2] = 0.f;
                    cx[i][j][0] = 0u; cx[i][j][1] = 0u;
                }

            int brow = tc + bnp;
#pragma unroll
            for (int ks = 0; ks < 4; ks++) {
                uint32_t bh[4];
                ldsm4(bh, uSkh + sw128((uint32_t)(brow * 128 + (ks * 16 + bkq) * 2)));
                mma_h32(cs[0][0], qh[ks][0], bh + 0);
                mma_h32(cs[0][1], qh[ks][0], bh + 2);
                mma_h32(cs[1][0], qh[ks][1], bh + 0);
                mma_h32(cs[1][1], qh[ks][1], bh + 2);
                mma_h16(cx[0][0], ql[ks][0], bh + 0);
                mma_h16(cx[0][1], ql[ks][0], bh + 2);
                mma_h16(cx[1][0], ql[ks][1], bh + 0);
                mma_h16(cx[1][1], ql[ks][1], bh + 2);
            }

            float2 xa0 = __half22float2(*(__half2*)&cx[0][0][0]);
            float2 xa1 = __half22float2(*(__half2*)&cx[0][1][0]);
            float2 xb0 = __half22float2(*(__half2*)&cx[0][0][1]);
            float2 xb1 = __half22float2(*(__half2*)&cx[0][1][1]);
            float2 xc0 = __half22float2(*(__half2*)&cx[1][0][0]);
            float2 xc1 = __half22float2(*(__half2*)&cx[1][1][0]);
            float2 xd0 = __half22float2(*(__half2*)&cx[1][0][1]);
            float2 xd1 = __half22float2(*(__half2*)&cx[1][1][1]);

            float wA0 = __expf(cs[0][0][0] + xa0.x + r00.x * SCALE) * invA;
            float wA1 = __expf(cs[0][0][1] + xa0.y + r00.y * SCALE) * invA;
            float wA2 = __expf(cs[0][1][0] + xa1.x + r01.x * SCALE) * invA;
            float wA3 = __expf(cs[0][1][1] + xa1.y + r01.y * SCALE) * invA;
            float wB0 = __expf(cs[0][0][2] + xb0.x + r10.x * SCALE) * invB;
            float wB1 = __expf(cs[0][0][3] + xb0.y + r10.y * SCALE) * invB;
            float wB2 = __expf(cs[0][1][2] + xb1.x + r11.x * SCALE) * invB;
            float wB3 = __expf(cs[0][1][3] + xb1.y + r11.y * SCALE) * invB;
            float wC0 = __expf(cs[1][0][0] + xc0.x + r20.x * SCALE) * invC;
            float wC1 = __expf(cs[1][0][1] + xc0.y + r20.y * SCALE) * invC;
            float wC2 = __expf(cs[1][1][0] + xc1.x + r21.x * SCALE) * invC;
            float wC3 = __expf(cs[1][1][1] + xc1.y + r21.y * SCALE) * invC;
            float wD0 = __expf(cs[1][0][2] + xd0.x + r30.x * SCALE) * invD;
            float wD1 = __expf(cs[1][0][3] + xd0.y + r30.y * SCALE) * invD;
            float wD2 = __expf(cs[1][1][2] + xd1.x + r31.x * SCALE) * invD;
            float wD3 = __expf(cs[1][1][3] + xd1.y + r31.y * SCALE) * invD;

            *(float2*)&wrow[(size_t)rA * S + cg]     = make_float2(wA0, wA1);
            *(float2*)&wrow[(size_t)rA * S + cg + 8] = make_float2(wA2, wA3);
            *(float2*)&wrow[(size_t)rB * S + cg]     = make_float2(wB0, wB1);
            *(float2*)&wrow[(size_t)rB * S + cg + 8] = make_float2(wB2, wB3);
            *(float2*)&wrow[(size_t)rC * S + cg]     = make_float2(wC0, wC1);
            *(float2*)&wrow[(size_t)rC * S + cg + 8] = make_float2(wC2, wC3);
            *(float2*)&wrow[(size_t)rD * S + cg]     = make_float2(wD0, wD1);
            *(float2*)&wrow[(size_t)rD * S + cg + 8] = make_float2(wD2, wD3);

            uint32_t ah0[4], al0[4], ah1[4], al1[4];
            split2h(wA0, wA1, ah0[0], al0[0]);
            split2h(wB0, wB1, ah0[1], al0[1]);
            split2h(wA2, wA3, ah0[2], al0[2]);
            split2h(wB2, wB3, ah0[3], al0[3]);
            split2h(wC0, wC1, ah1[0], al1[0]);
            split2h(wD0, wD1, ah1[1], al1[1]);
            split2h(wC2, wC3, ah1[2], al1[2]);
            split2h(wD2, wD3, ah1[3], al1[3]);

            // PV for this chunk: chunk-local f16 cross accumulators, folded
            int sub = tc >> 6;
            uint32_t cb = (uint32_t)(((tc & 63) + bkq) * 2);
            uint32_t oxl[2][8][2];
#pragma unroll
            for (int i = 0; i < 2; i++)
#pragma unroll
                for (int j = 0; j < 8; j++) { oxl[i][j][0] = 0u; oxl[i][j][1] = 0u; }
#pragma unroll
            for (int jd = 0; jd < 4; jd++) {
                int dn = jd * 16 + bnp;
                uint32_t vh[4];
                ldsm4(vh, vbuf + sub * 8192 + sw128((uint32_t)(dn * 128 + cb)));
                mma_h32(o[0][jd * 2 + 0], ah0, vh + 0);
                mma_h32(o[0][jd * 2 + 1], ah0, vh + 2);
                mma_h32(o[1][jd * 2 + 0], ah1, vh + 0);
                mma_h32(o[1][jd * 2 + 1], ah1, vh + 2);
                mma_h16(oxl[0][jd * 2 + 0], al0, vh + 0);
                mma_h16(oxl[0][jd * 2 + 1], al0, vh + 2);
                mma_h16(oxl[1][jd * 2 + 0], al1, vh + 0);
                mma_h16(oxl[1][jd * 2 + 1], al1, vh + 2);
            }
            // fold cross terms into fp32 accumulators (frees oxl registers)
#pragma unroll
            for (int i = 0; i < 2; i++)
#pragma unroll
                for (int j = 0; j < 8; j++) {
                    float2 cl = __half22float2(*(__half2*)&oxl[i][j][0]);
                    float2 ch2 = __half22float2(*(__half2*)&oxl[i][j][1]);
                    o[i][j][0] += cl.x;  o[i][j][1] += cl.y;
                    o[i][j][2] += ch2.x; o[i][j][3] += ch2.y;
                }
        }
        __syncthreads();
    }

    // epilogue: combine PV partials across N-warps
    float* red = (float*)dyn;
    __syncthreads();
    if (wn == 0) {
#pragma unroll
        for (int i = 0; i < 2; i++)
#pragma unroll
            for (int j = 0; j < 8; j++) {
                int r = wm * 32 + i * 16 + g;
                int c = j * 8 + 2 * t4;
                *(float2*)&red[r * 64 + c] = make_float2(o[i][j][0], o[i][j][1]);
                *(float2*)&red[(r + 8) * 64 + c] = make_float2(o[i][j][2], o[i][j][3]);
            }
    }
    __syncthreads();
    if (wn == 1) {
#pragma unroll
        for (int i = 0; i < 2; i++)
#pragma unroll
            for (int j = 0; j < 8; j++) {
                int r = wm * 32 + i * 16 + g;
                int c = j * 8 + 2 * t4;
                float2 p0 = *(const float2*)&red[r * 64 + c];
                float2 p1 = *(const float2*)&red[(r + 8) * 64 + c];
                *(float2*)&g_attn[(size_t)(row0 + r) * E + qc0 + c] =
                    make_float2(o[i][j][0] + p0.x, o[i][j][1] + p0.y);
                *(float2*)&g_attn[(size_t)(row0 + r + 8) * E + qc0 + c] =
                    make_float2(o[i][j][2] + p1.x, o[i][j][3] + p1.y);
            }
    }
}

// ---------------------------------------------------------------------------
// Launch
// ---------------------------------------------------------------------------
extern "C" void kernel_launch(void* const* d_in, const int* in_sizes, int n_in,
                              void* d_out, int out_size)
{
    (void)in_sizes; (void)n_in; (void)out_size;
    const float* query = (const float*)d_in[0];
    const float* key   = (const float*)d_in[1];
    const float* value = (const float*)d_in[2];
    const float* sim   = (const float*)d_in[3];
    const float* bq    = (const float*)d_in[5];
    const float* bk    = (const float*)d_in[7];
    const float* bv    = (const float*)d_in[9];
    const float* Wq    = (const float*)d_in[4];
    const float* Wk    = (const float*)d_in[6];
    const float* Wv    = (const float*)d_in[8];
    const float* Wo    = (const float*)d_in[10];
    const float* bo    = (const float*)d_in[11];

    float* out = (float*)d_out;                 // [S,E]
    float* w   = out + (size_t)S * E;           // [H,S,S]

    float *grel;
    char *simAi, *simBi, *atti, *wi;
    cudaGetSymbolAddress((void**)&grel,  g_rel);
    cudaGetSymbolAddress((void**)&simAi, g_simAi);
    cudaGetSymbolAddress((void**)&simBi, g_simBi);
    cudaGetSymbolAddress((void**)&atti,  g_atti);
    cudaGetSymbolAddress((void**)&wi,    g_wi);

    static int attr_done = 0;
    if (!attr_done) {
        cudaFuncSetAttribute(fused_attn,
                             cudaFuncAttributeMaxDynamicSharedMemorySize, 49152);
        attr_done = 1;
    }

    // 0: convert GEMM operands to images
    prep_all<<<dim3(32, 32, 9), dim3(256)>>>(query, key, value, Wq, Wk, Wv, Wo, sim);

    // 1: q/k/v projections
    proj_img<<<dim3(E / 64, S / 128, 3), dim3(256)>>>(bq, bk, bv);

    // 2: pre-split k/v for fused attention
    prep_kv<<<dim3(NT, H), dim3(128)>>>();

    // 3: rel = sim @ sim^T
    tc_gemm_img<<<dim3(S / 64, S / 128), dim3(256)>>>(simAi, simBi, grel, 2, S, nullptr);

    // 4: fused attention
    fused_attn<<<dim3(S / 64, H), dim3(128), 49152>>>(grel, w);

    // 5: attn -> image
    prep_attn<<<dim3(32, 16), dim3(256)>>>();

    // 6: out = attn @ Wo^T + bo
    tc_gemm_img<<<dim3(E / 64, S / 128), dim3(256)>>>(atti, wi + (size_t)3 * 4194304u,
                                                      out, 32, E, bo);
}